// round 11
// baseline (speedup 1.0000x reference)
#include <cuda_runtime.h>
#include <cuda_fp16.h>
#include <cstdint>

#define NB 4
#define NH 8
#define NT 2048
#define DH 32
#define NC 256
#define SCALE 0.17677669529663687f
#define L2E   1.4426950408889634f

static __device__ __half g_q[(size_t)NB*NH*NT*DH];
static __device__ __half g_k[(size_t)NB*NH*NT*DH];
static __device__ __half g_v[(size_t)NB*NH*NT*DH];
static __device__ float  g_x[(size_t)NB*NT*NC];
static __device__ float  g_icm[NB*NT];
static __device__ float  g_cmp[(size_t)NB*32*NT];
static __device__ __half g_mh[(size_t)NB*NT*NT];   // transposed, UNnormalized

__device__ __forceinline__ float fast_ex2(float x){
    float y; asm("ex2.approx.ftz.f32 %0, %1;" : "=f"(y) : "f"(x)); return y;
}
__device__ __forceinline__ void mma16816(float* c, const unsigned* a, unsigned b0, unsigned b1){
    asm volatile("mma.sync.aligned.m16n8k16.row.col.f32.f16.f16.f32 "
        "{%0,%1,%2,%3},{%4,%5,%6,%7},{%8,%9},{%0,%1,%2,%3};"
        : "+f"(c[0]), "+f"(c[1]), "+f"(c[2]), "+f"(c[3])
        : "r"(a[0]), "r"(a[1]), "r"(a[2]), "r"(a[3]), "r"(b0), "r"(b1));
}
__device__ __forceinline__ uint32_t s2u(const void* p){
    return (uint32_t)__cvta_generic_to_shared(p);
}
__device__ __forceinline__ void ldsm_x4(unsigned* a, uint32_t addr){
    asm volatile("ldmatrix.sync.aligned.m8n8.x4.shared.b16 {%0,%1,%2,%3}, [%4];"
        : "=r"(a[0]),"=r"(a[1]),"=r"(a[2]),"=r"(a[3]) : "r"(addr));
}
__device__ __forceinline__ void ldsm_x2(unsigned& b0, unsigned& b1, uint32_t addr){
    asm volatile("ldmatrix.sync.aligned.m8n8.x2.shared.b16 {%0,%1}, [%2];"
        : "=r"(b0),"=r"(b1) : "r"(addr));
}
__device__ __forceinline__ void ldsm_x2t(unsigned& b0, unsigned& b1, uint32_t addr){
    asm volatile("ldmatrix.sync.aligned.m8n8.x2.trans.shared.b16 {%0,%1}, [%2];"
        : "=r"(b0),"=r"(b1) : "r"(addr));
}
#define CPA16(dst, src) asm volatile("cp.async.cg.shared.global [%0], [%1], 16;" :: "r"(dst), "l"(src))
#define CPA_COMMIT() asm volatile("cp.async.commit_group;")
#define CPA_WAIT1()  asm volatile("cp.async.wait_group 1;" ::: "memory")
#define CPA_WAIT0()  asm volatile("cp.async.wait_group 0;" ::: "memory")

// normalize one 512-col chunk of one owned row: vis = E*inv (fp32 STG.128),
// masked probs = E*mask*inv*icm (half, back into sS in place)
#define NORM1(srow, mrow, orow, invf, invh2, cc) do { \
    _Pragma("unroll") \
    for (int s_ = 0; s_ < 2; s_++){ \
        int j8_ = ((cc)*512 + (s_*32 + lane)*8); \
        uint4 u_ = *(uint4*)&(srow)[j8_]; \
        uint4 mu_ = *(const uint4*)&(mrow)[j8_]; \
        __half2 e0_=*(__half2*)&u_.x, e1_=*(__half2*)&u_.y; \
        __half2 e2_=*(__half2*)&u_.z, e3_=*(__half2*)&u_.w; \
        float2 f0_=__half22float2(e0_), f1_=__half22float2(e1_); \
        float2 f2_=__half22float2(e2_), f3_=__half22float2(e3_); \
        float4 v0_, v1_; \
        v0_.x=f0_.x*(invf); v0_.y=f0_.y*(invf); v0_.z=f1_.x*(invf); v0_.w=f1_.y*(invf); \
        v1_.x=f2_.x*(invf); v1_.y=f2_.y*(invf); v1_.z=f3_.x*(invf); v1_.w=f3_.y*(invf); \
        *(float4*)&(orow)[j8_]     = v0_; \
        *(float4*)&(orow)[j8_ + 4] = v1_; \
        __half2 p0_=__hmul2(__hmul2(e0_,*(__half2*)&mu_.x),(invh2)); \
        __half2 p1_=__hmul2(__hmul2(e1_,*(__half2*)&mu_.y),(invh2)); \
        __half2 p2_=__hmul2(__hmul2(e2_,*(__half2*)&mu_.z),(invh2)); \
        __half2 p3_=__hmul2(__hmul2(e3_,*(__half2*)&mu_.w),(invh2)); \
        uint4 w_; \
        w_.x=*reinterpret_cast<unsigned*>(&p0_); \
        w_.y=*reinterpret_cast<unsigned*>(&p1_); \
        w_.z=*reinterpret_cast<unsigned*>(&p2_); \
        w_.w=*reinterpret_cast<unsigned*>(&p3_); \
        *(uint4*)&(srow)[j8_] = w_; \
    } \
} while(0)

// ---------------- fused mask transpose + column-max partials ----------------
__global__ __launch_bounds__(256) void mask_prep_kernel(const float* __restrict__ mask){
    __shared__ float t[64][65];
    __shared__ float pm[8][64];
    int b = blockIdx.z;
    int k0 = blockIdx.x * 64, q0 = blockIdx.y * 64;
    const int tid = threadIdx.x;
#pragma unroll
    for (int i = 0; i < 4; i++){
        int e = tid + i*256, r = e >> 4, c4 = e & 15;
        float4 v = *(const float4*)&mask[(size_t)b*NT*NT + (size_t)(k0 + r)*NT + q0 + c4*4];
        t[r][c4*4    ] = v.x; t[r][c4*4 + 1] = v.y;
        t[r][c4*4 + 2] = v.z; t[r][c4*4 + 3] = v.w;
    }
    __syncthreads();
#pragma unroll
    for (int i = 0; i < 2; i++){
        int idx = tid + i*256;
        int q = idx >> 3, seg = idx & 7;
        float f0 = t[seg*8    ][q], f1 = t[seg*8 + 1][q];
        float f2 = t[seg*8 + 2][q], f3 = t[seg*8 + 3][q];
        float f4 = t[seg*8 + 4][q], f5 = t[seg*8 + 5][q];
        float f6 = t[seg*8 + 6][q], f7 = t[seg*8 + 7][q];
        __half2 h0 = __floats2half2_rn(f0, f1), h1 = __floats2half2_rn(f2, f3);
        __half2 h2 = __floats2half2_rn(f4, f5), h3 = __floats2half2_rn(f6, f7);
        uint4 w;
        w.x = *reinterpret_cast<unsigned*>(&h0);
        w.y = *reinterpret_cast<unsigned*>(&h1);
        w.z = *reinterpret_cast<unsigned*>(&h2);
        w.w = *reinterpret_cast<unsigned*>(&h3);
        *(uint4*)&g_mh[((size_t)b*NT + q0 + q)*NT + k0 + seg*8] = w;
        float m = fmaxf(fmaxf(fmaxf(f0, f1), fmaxf(f2, f3)),
                        fmaxf(fmaxf(f4, f5), fmaxf(f6, f7)));
        pm[seg][q] = m;
    }
    __syncthreads();
    if (tid < 64){
        float m3 = pm[0][tid];
#pragma unroll
        for (int w2 = 1; w2 < 8; w2++) m3 = fmaxf(m3, pm[w2][tid]);
        g_cmp[((size_t)b*32 + (k0 >> 6))*NT + q0 + tid] = m3;
    }
}
__global__ void colmax_fin(){
    int i = blockIdx.x*256 + threadIdx.x;
    int b = i >> 11, q = i & (NT-1);
    float mx = 0.f;
#pragma unroll
    for (int s = 0; s < 32; s++) mx = fmaxf(mx, g_cmp[((size_t)b*32 + s)*NT + q]);
    g_icm[i] = 1.0f / mx;
}

// ---------------- GEMM: OUT[8192,256] = X @ W^T + bias ----------------
template<bool OUTPROJ>
__global__ __launch_bounds__(256) void gemm_kernel(
    const float* __restrict__ Xin,
    const float* __restrict__ Wa, const float* __restrict__ ba,
    const float* __restrict__ Wb, const float* __restrict__ bb_,
    const float* __restrict__ Wc, const float* __restrict__ bc,
    const float* __restrict__ resid, float* __restrict__ outF)
{
    __shared__ __half sA[128*72];
    __shared__ __half sB[64*72];
    const float* X = OUTPROJ ? (const float*)g_x : Xin;   // device-side symbol!
    const int m0 = blockIdx.x * 128, j0 = blockIdx.y * 64;
    const int pz = blockIdx.z;
    const float* W    = (pz == 0) ? Wa : (pz == 1) ? Wb : Wc;
    const float* bias = (pz == 0) ? ba : (pz == 1) ? bb_ : bc;
    __half* outH      = (pz == 0) ? g_q : (pz == 1) ? g_k : g_v;
    const float osc   = (!OUTPROJ && pz == 0) ? SCALE : 1.0f;

    const int tid = threadIdx.x, lane = tid & 31, wid = tid >> 5;
    const int wm = wid >> 1, wn = wid & 1;

    float acc[2][4][4];
#pragma unroll
    for (int m = 0; m < 2; m++)
#pragma unroll
        for (int nt = 0; nt < 4; nt++)
#pragma unroll
            for (int i = 0; i < 4; i++) acc[m][nt][i] = 0.f;

    for (int k0 = 0; k0 < NC; k0 += 64){
        __syncthreads();
#pragma unroll
        for (int i = 0; i < 8; i++){
            int e = tid + i*256, r = e >> 4, c4 = e & 15;
            float4 v = *(const float4*)&X[(size_t)(m0 + r)*NC + k0 + c4*4];
            *(__half2*)&sA[r*72 + c4*4]     = __floats2half2_rn(v.x, v.y);
            *(__half2*)&sA[r*72 + c4*4 + 2] = __floats2half2_rn(v.z, v.w);
        }
#pragma unroll
        for (int i = 0; i < 4; i++){
            int e = tid + i*256, r = e >> 4, c4 = e & 15;
            float4 v = *(const float4*)&W[(size_t)(j0 + r)*NC + k0 + c4*4];
            *(__half2*)&sB[r*72 + c4*4]     = __floats2half2_rn(v.x, v.y);
            *(__half2*)&sB[r*72 + c4*4 + 2] = __floats2half2_rn(v.z, v.w);
        }
        __syncthreads();
#pragma unroll
        for (int kk = 0; kk < 4; kk++){
            int dc = kk*16 + 2*(lane & 3);
            unsigned a[2][4], bb[4][2];
#pragma unroll
            for (int m = 0; m < 2; m++){
                int r = wm*32 + m*16 + (lane >> 2);
                a[m][0] = *(const unsigned*)&sA[r*72 + dc];
                a[m][1] = *(const unsigned*)&sA[(r + 8)*72 + dc];
                a[m][2] = *(const unsigned*)&sA[r*72 + dc + 8];
                a[m][3] = *(const unsigned*)&sA[(r + 8)*72 + dc + 8];
            }
#pragma unroll
            for (int nt = 0; nt < 4; nt++){
                int rj = wn*32 + nt*8 + (lane >> 2);
                bb[nt][0] = *(const unsigned*)&sB[rj*72 + dc];
                bb[nt][1] = *(const unsigned*)&sB[rj*72 + dc + 8];
            }
#pragma unroll
            for (int m = 0; m < 2; m++)
#pragma unroll
                for (int nt = 0; nt < 4; nt++)
                    mma16816(acc[m][nt], a[m], bb[nt][0], bb[nt][1]);
        }
    }

#pragma unroll
    for (int m = 0; m < 2; m++)
#pragma unroll
        for (int nt = 0; nt < 4; nt++){
            int row = m0 + wm*32 + m*16 + (lane >> 2);
            int col = j0 + wn*32 + nt*8 + 2*(lane & 3);
            float b0f = bias[col], b1f = bias[col + 1];
#pragma unroll
            for (int rg = 0; rg < 2; rg++){
                int rr = row + rg*8;
                if (OUTPROJ){
                    float2 o;
                    o.x = acc[m][nt][rg*2 + 0] + b0f + resid[(size_t)rr*NC + col];
                    o.y = acc[m][nt][rg*2 + 1] + b1f + resid[(size_t)rr*NC + col + 1];
                    *(float2*)&outF[(size_t)rr*NC + col] = o;
                } else {
                    int bb2 = rr >> 11, n = rr & (NT-1);
                    int hh = col >> 5, dd = col & 31;
                    size_t addr = ((size_t)(bb2*NH + hh)*NT + n)*DH + dd;
                    *(__half2*)&outH[addr] =
                        __floats2half2_rn((acc[m][nt][rg*2 + 0] + b0f)*osc,
                                          (acc[m][nt][rg*2 + 1] + b1f)*osc);
                }
            }
        }
}

// ------------- fused attention (TQ=32, 512 threads, pipelined norm+AV) -------------
#define TQ 32
#define CHUNK 512
#define NCH (NT/CHUNK)                       // 4
#define NWARP 16
#define SS_STRIDE 2056
#define SK_STRIDE 40
#define KVBUF (CHUNK*SK_STRIDE)              // halves per buffer
#define OFF_S   0
#define SZ_S    (TQ*SS_STRIDE*2)             // 131584
#define OFF_KV  (SZ_S)
#define SZ_KV   (2*KVBUF*2)                  // 81920
#define OFF_Q   (OFF_KV + SZ_KV)             // 213504
#define SZ_Q    (TQ*SK_STRIDE*2)             // 2560
#define OFF_SUM (OFF_Q + SZ_Q)               // 216064
#define SMEM_ATTN (OFF_SUM + NWARP*TQ*4)     // 218112 -> 1 CTA/SM

__global__ __launch_bounds__(512, 1) void attn_kernel(float* __restrict__ attn_out)
{
    extern __shared__ char smem[];
    __half* sS   = (__half*)(smem + OFF_S);
    __half* sKV  = (__half*)(smem + OFF_KV);   // [2][KVBUF]
    __half* sQ   = (__half*)(smem + OFF_Q);
    float*  sSum = (float*)(smem + OFF_SUM);

    const int h = blockIdx.x, qt = blockIdx.y, b = blockIdx.z;
    const int bh = b*NH + h;
    const int q0 = qt*TQ;
    const int tid = threadIdx.x, lane = tid & 31, wid = tid >> 5;

    const __half* gQ = g_q + ((size_t)bh*NT + q0)*DH;
    const __half* gK = g_k + (size_t)bh*NT*DH;
    const __half* gV = g_v + (size_t)bh*NT*DH;

    if (tid < 128){
        int r = tid >> 2, seg = tid & 3;
        *(uint4*)&sQ[r*SK_STRIDE + seg*8] = *(const uint4*)&gQ[r*DH + seg*8];
    }

    const int ld_r = tid >> 2, ld_seg = tid & 3;   // 512 rows x 4 segs / 512 thr = 4 CPA16

    // ---- Phase 1: E = exp(Q K^T), double-buffered K ----
    {
        __half* buf = sKV;
#pragma unroll
        for (int i = 0; i < 4; i++){
            int r = ld_r + i*128;
            CPA16(s2u(&buf[r*SK_STRIDE + ld_seg*8]), &gK[(size_t)r*DH + ld_seg*8]);
        }
        CPA_COMMIT();
    }
    unsigned aq[2][2][4];
    float s0 = 0.f, s1 = 0.f, s2 = 0.f, s3 = 0.f;
    for (int ct = 0; ct < NCH; ct++){
        __syncthreads();   // prev compute done -> safe to overwrite idle buffer
        if (ct + 1 < NCH){
            __half* buf = sKV + ((ct + 1) & 1)*KVBUF;
#pragma unroll
            for (int i = 0; i < 4; i++){
                int r = ld_r + i*128;
                CPA16(s2u(&buf[r*SK_STRIDE + ld_seg*8]),
                      &gK[(size_t)((ct + 1)*CHUNK + r)*DH + ld_seg*8]);
            }
            CPA_COMMIT();
            CPA_WAIT1();
        } else {
            CPA_WAIT0();
        }
        __syncthreads();   // chunk ct visible to all
        const __half* kb = sKV + (ct & 1)*KVBUF;
        if (ct == 0){
            uint32_t qa0 = s2u(&sQ[(lane & 15)*SK_STRIDE + 8*(lane >> 4)]);
            ldsm_x4(aq[0][0], qa0);
            ldsm_x4(aq[0][1], qa0 + 32);                       // rows 0-15, k16-31
            uint32_t qa1 = qa0 + 16*SK_STRIDE*2;
            ldsm_x4(aq[1][0], qa1);
            ldsm_x4(aq[1][1], qa1 + 32);                       // rows 16-31
        }
#pragma unroll
        for (int nt = 0; nt < 4; nt++){
            int t0 = wid*32 + nt*8;
            uint32_t ba = s2u(&kb[(t0 + (lane & 7))*SK_STRIDE + 8*((lane >> 3) & 1)]);
            float c0[4] = {0.f,0.f,0.f,0.f}, c1[4] = {0.f,0.f,0.f,0.f};
            unsigned b0, b1;
            ldsm_x2(b0, b1, ba);
            mma16816(c0, aq[0][0], b0, b1);
            mma16816(c1, aq[1][0], b0, b1);
            ldsm_x2(b0, b1, ba + 32);
            mma16816(c0, aq[0][1], b0, b1);
            mma16816(c1, aq[1][1], b0, b1);
            float e00 = fast_ex2(c0[0]*L2E), e01 = fast_ex2(c0[1]*L2E);
            float e02 = fast_ex2(c0[2]*L2E), e03 = fast_ex2(c0[3]*L2E);
            float e10 = fast_ex2(c1[0]*L2E), e11 = fast_ex2(c1[1]*L2E);
            float e12 = fast_ex2(c1[2]*L2E), e13 = fast_ex2(c1[3]*L2E);
            s0 += e00 + e01; s1 += e02 + e03;
            s2 += e10 + e11; s3 += e12 + e13;
            int gc = ct*CHUNK + t0 + 2*(lane & 3);
            int r0 = lane >> 2;
            *(__half2*)&sS[(r0     )*SS_STRIDE + gc] = __floats2half2_rn(e00, e01);
            *(__half2*)&sS[(r0 +  8)*SS_STRIDE + gc] = __floats2half2_rn(e02, e03);
            *(__half2*)&sS[(r0 + 16)*SS_STRIDE + gc] = __floats2half2_rn(e10, e11);
            *(__half2*)&sS[(r0 + 24)*SS_STRIDE + gc] = __floats2half2_rn(e12, e13);
        }
    }
    // reduce row partials across the 4 lanes sharing a row, stage per warp
    s0 += __shfl_xor_sync(0xffffffffu, s0, 1); s0 += __shfl_xor_sync(0xffffffffu, s0, 2);
    s1 += __shfl_xor_sync(0xffffffffu, s1, 1); s1 += __shfl_xor_sync(0xffffffffu, s1, 2);
    s2 += __shfl_xor_sync(0xffffffffu, s2, 1); s2 += __shfl_xor_sync(0xffffffffu, s2, 2);
    s3 += __shfl_xor_sync(0xffffffffu, s3, 1); s3 += __shfl_xor_sync(0xffffffffu, s3, 2);
    if ((lane & 3) == 0){
        int r0 = lane >> 2;
        sSum[wid*TQ + r0]      = s0;
        sSum[wid*TQ + r0 + 8]  = s1;
        sSum[wid*TQ + r0 + 16] = s2;
        sSum[wid*TQ + r0 + 24] = s3;
    }
    __syncthreads();   // sS (all E) + sSum visible

    // prefetch V chunk 0 (overlaps the prologue normalize below)
    {
        __half* buf = sKV;
#pragma unroll
        for (int i = 0; i < 4; i++){
            int r = ld_r + i*128;
            CPA16(s2u(&buf[r*SK_STRIDE + ld_seg*8]), &gV[(size_t)r*DH + ld_seg*8]);
        }
        CPA_COMMIT();
    }

    // per-warp row constants (each warp owns rows wid*2, wid*2+1)
    const int row0 = wid*2, row1 = wid*2 + 1;
    float svA = 0.f, svB = 0.f;
#pragma unroll
    for (int w = 0; w < NWARP; w++){
        svA += sSum[w*TQ + row0];
        svB += sSum[w*TQ + row1];
    }
    const float invA = 1.0f/svA, invB = 1.0f/svB;
    const __half2 invA2 = __float2half2_rn(invA * g_icm[b*NT + q0 + row0]);
    const __half2 invB2 = __float2half2_rn(invB * g_icm[b*NT + q0 + row1]);
    __half* srowA = &sS[row0*SS_STRIDE];
    __half* srowB = &sS[row1*SS_STRIDE];
    const __half* mrowA = g_mh + ((size_t)b*NT + q0 + row0)*NT;
    const __half* mrowB = g_mh + ((size_t)b*NT + q0 + row1)*NT;
    float* orowA = attn_out + ((size_t)bh*NT + q0 + row0)*NT;
    float* orowB = attn_out + ((size_t)bh*NT + q0 + row1)*NT;

    // prologue: normalize chunk 0 (row-owned; E written before the barrier above)
    NORM1(srowA, mrowA, orowA, invA, invA2, 0);
    NORM1(srowB, mrowB, orowB, invB, invB2, 0);

    // ---- fused AV + pipelined normalize (one chunk ahead) ----
    float acc[2][4][4];
#pragma unroll
    for (int rt = 0; rt < 2; rt++)
#pragma unroll
        for (int nt = 0; nt < 4; nt++)
#pragma unroll
            for (int i = 0; i < 4; i++) acc[rt][nt][i] = 0.f;

    for (int ct = 0; ct < NCH; ct++){
        __syncthreads();   // probs(ct) from all warps visible; V buf[(ct+1)&1] free
        if (ct + 1 < NCH){
            __half* buf = sKV + ((ct + 1) & 1)*KVBUF;
#pragma unroll
            for (int i = 0; i < 4; i++){
                int r = ld_r + i*128;
                CPA16(s2u(&buf[r*SK_STRIDE + ld_seg*8]),
                      &gV[(size_t)((ct + 1)*CHUNK + r)*DH + ld_seg*8]);
            }
            CPA_COMMIT();
            CPA_WAIT1();
        } else {
            CPA_WAIT0();
        }
        __syncthreads();   // V chunk ct visible
        const __half* vb = sKV + (ct & 1)*KVBUF;
#pragma unroll
        for (int kb = 0; kb < 2; kb++){
            int tc = wid*32 + kb*16;
            int gcol = ct*CHUNK + tc;
            unsigned a0[4], a1[4];
            ldsm_x4(a0, s2u(&sS[(lane & 15)*SS_STRIDE + gcol + 8*(lane >> 4)]));
            ldsm_x4(a1, s2u(&sS[((lane & 15) + 16)*SS_STRIDE + gcol + 8*(lane >> 4)]));
#pragma unroll
            for (int nt = 0; nt < 4; nt++){
                unsigned b0, b1;
                ldsm_x2t(b0, b1, s2u(&vb[(tc + (lane & 15))*SK_STRIDE + nt*8]));
                mma16816(acc[0][nt], a0, b0, b1);
                mma16816(acc[1][nt], a1, b0, b1);
            }
        }
        // normalize chunk ct+1 while MMAs are in flight (disjoint columns)
        if (ct + 1 < NCH){
            NORM1(srowA, mrowA, orowA, invA, invA2, ct + 1);
            NORM1(srowB, mrowB, orowB, invB, invB2, ct + 1);
        }
    }

    // ---- cross-warp AV reduction (reuse sS region: 16 x 1024 floats = 64KB) ----
    __syncthreads();
    const int r_lo = lane >> 2, r_hi = r_lo + 8;
    float* sRed = (float*)(smem + OFF_S);
#pragma unroll
    for (int rt = 0; rt < 2; rt++)
#pragma unroll
        for (int nt = 0; nt < 4; nt++){
            int dd = nt*8 + 2*(lane & 3);
            float2 v0; v0.x = acc[rt][nt][0]; v0.y = acc[rt][nt][1];
            float2 v1; v1.x = acc[rt][nt][2]; v1.y = acc[rt][nt][3];
            *(float2*)&sRed[wid*1024 + (r_lo + rt*16)*32 + dd] = v0;
            *(float2*)&sRed[wid*1024 + (r_hi + rt*16)*32 + dd] = v1;
        }
    __syncthreads();
#pragma unroll
    for (int ii = 0; ii < 2; ii++){
        int i = tid + ii*512;
        float s = 0.f;
#pragma unroll
        for (int w = 0; w < NWARP; w++) s += sRed[w*1024 + i];
        int qq = i >> 5, dd = i & 31;
        g_x[((size_t)b*NT + q0 + qq)*NC + h*DH + dd] = s;
    }
}

// ---------------- launch ----------------
extern "C" void kernel_launch(void* const* d_in, const int* in_sizes, int n_in,
                              void* d_out, int out_size)
{
    const float* query = (const float*)d_in[0];
    const float* mask  = (const float*)d_in[1];
    const float* Wq = (const float*)d_in[2]; const float* bq = (const float*)d_in[3];
    const float* Wk = (const float*)d_in[4]; const float* bk = (const float*)d_in[5];
    const float* Wv = (const float*)d_in[6]; const float* bv = (const float*)d_in[7];
    const float* Wo = (const float*)d_in[8]; const float* bo = (const float*)d_in[9];

    float* out_query = (float*)d_out;
    float* attn_vis  = out_query + (size_t)NB*NT*NC;

    cudaFuncSetAttribute(attn_kernel, cudaFuncAttributeMaxDynamicSharedMemorySize, SMEM_ATTN);

    mask_prep_kernel<<<dim3(NT/64, NT/64, NB), 256>>>(mask);
    colmax_fin<<<NB*NT/256, 256>>>();
    gemm_kernel<false><<<dim3(NB*NT/128, NC/64, 3), 256>>>(
        query, Wq, bq, Wk, bk, Wv, bv, nullptr, nullptr);
    attn_kernel<<<dim3(NH, NT/TQ, NB), 512, SMEM_ATTN>>>(attn_vis);
    gemm_kernel<true><<<dim3(NB*NT/128, NC/64, 1), 256>>>(
        nullptr, Wo, bo, nullptr, nullptr, nullptr, nullptr, query, out_query);
}

// round 12
// speedup vs baseline: 1.0815x; 1.0815x over previous
#include <cuda_runtime.h>
#include <cuda_fp16.h>
#include <cstdint>

#define NB 4
#define NH 8
#define NT 2048
#define DH 32
#define NC 256
#define SCALE 0.17677669529663687f
#define L2E   1.4426950408889634f

static __device__ __half g_q[(size_t)NB*NH*NT*DH];
static __device__ __half g_k[(size_t)NB*NH*NT*DH];
static __device__ __half g_v[(size_t)NB*NH*NT*DH];
static __device__ float  g_x[(size_t)NB*NT*NC];
static __device__ float  g_cmp[(size_t)NB*32*NT];
static __device__ __half g_mh[(size_t)NB*NT*NT];   // transposed, UNnormalized

__device__ __forceinline__ float fast_ex2(float x){
    float y; asm("ex2.approx.ftz.f32 %0, %1;" : "=f"(y) : "f"(x)); return y;
}
__device__ __forceinline__ void mma16816(float* c, const unsigned* a, unsigned b0, unsigned b1){
    asm volatile("mma.sync.aligned.m16n8k16.row.col.f32.f16.f16.f32 "
        "{%0,%1,%2,%3},{%4,%5,%6,%7},{%8,%9},{%0,%1,%2,%3};"
        : "+f"(c[0]), "+f"(c[1]), "+f"(c[2]), "+f"(c[3])
        : "r"(a[0]), "r"(a[1]), "r"(a[2]), "r"(a[3]), "r"(b0), "r"(b1));
}
__device__ __forceinline__ uint32_t s2u(const void* p){
    return (uint32_t)__cvta_generic_to_shared(p);
}
__device__ __forceinline__ void ldsm_x4(unsigned* a, uint32_t addr){
    asm volatile("ldmatrix.sync.aligned.m8n8.x4.shared.b16 {%0,%1,%2,%3}, [%4];"
        : "=r"(a[0]),"=r"(a[1]),"=r"(a[2]),"=r"(a[3]) : "r"(addr));
}
__device__ __forceinline__ void ldsm_x2(unsigned& b0, unsigned& b1, uint32_t addr){
    asm volatile("ldmatrix.sync.aligned.m8n8.x2.shared.b16 {%0,%1}, [%2];"
        : "=r"(b0),"=r"(b1) : "r"(addr));
}
__device__ __forceinline__ void ldsm_x2t(unsigned& b0, unsigned& b1, uint32_t addr){
    asm volatile("ldmatrix.sync.aligned.m8n8.x2.trans.shared.b16 {%0,%1}, [%2];"
        : "=r"(b0),"=r"(b1) : "r"(addr));
}
#define CPA16(dst, src) asm volatile("cp.async.cg.shared.global [%0], [%1], 16;" :: "r"(dst), "l"(src))
#define CPA_COMMIT() asm volatile("cp.async.commit_group;")
#define CPA_WAIT1()  asm volatile("cp.async.wait_group 1;" ::: "memory")
#define CPA_WAIT0()  asm volatile("cp.async.wait_group 0;" ::: "memory")

// ---------------- fused mask transpose + column-max partials ----------------
__global__ __launch_bounds__(256) void mask_prep_kernel(const float* __restrict__ mask){
    __shared__ float t[64][65];
    __shared__ float pm[8][64];
    int b = blockIdx.z;
    int k0 = blockIdx.x * 64, q0 = blockIdx.y * 64;
    const int tid = threadIdx.x;
#pragma unroll
    for (int i = 0; i < 4; i++){
        int e = tid + i*256, r = e >> 4, c4 = e & 15;
        float4 v = *(const float4*)&mask[(size_t)b*NT*NT + (size_t)(k0 + r)*NT + q0 + c4*4];
        t[r][c4*4    ] = v.x; t[r][c4*4 + 1] = v.y;
        t[r][c4*4 + 2] = v.z; t[r][c4*4 + 3] = v.w;
    }
    __syncthreads();
#pragma unroll
    for (int i = 0; i < 2; i++){
        int idx = tid + i*256;
        int q = idx >> 3, seg = idx & 7;
        float f0 = t[seg*8    ][q], f1 = t[seg*8 + 1][q];
        float f2 = t[seg*8 + 2][q], f3 = t[seg*8 + 3][q];
        float f4 = t[seg*8 + 4][q], f5 = t[seg*8 + 5][q];
        float f6 = t[seg*8 + 6][q], f7 = t[seg*8 + 7][q];
        __half2 h0 = __floats2half2_rn(f0, f1), h1 = __floats2half2_rn(f2, f3);
        __half2 h2 = __floats2half2_rn(f4, f5), h3 = __floats2half2_rn(f6, f7);
        uint4 w;
        w.x = *reinterpret_cast<unsigned*>(&h0);
        w.y = *reinterpret_cast<unsigned*>(&h1);
        w.z = *reinterpret_cast<unsigned*>(&h2);
        w.w = *reinterpret_cast<unsigned*>(&h3);
        *(uint4*)&g_mh[((size_t)b*NT + q0 + q)*NT + k0 + seg*8] = w;
        float m = fmaxf(fmaxf(fmaxf(f0, f1), fmaxf(f2, f3)),
                        fmaxf(fmaxf(f4, f5), fmaxf(f6, f7)));
        pm[seg][q] = m;
    }
    __syncthreads();
    if (tid < 64){
        float m3 = pm[0][tid];
#pragma unroll
        for (int w2 = 1; w2 < 8; w2++) m3 = fmaxf(m3, pm[w2][tid]);
        // two 64-row k-tiles per 32-slice index? no: one partial per 64-k tile,
        // stored at slice k0/64 in a 32-slice table
        g_cmp[((size_t)b*32 + (k0 >> 6))*NT + q0 + tid] = m3;
    }
}

// ---------------- GEMM: OUT[8192,256] = X @ W^T + bias ----------------
template<bool OUTPROJ>
__global__ __launch_bounds__(256) void gemm_kernel(
    const float* __restrict__ Xin,
    const float* __restrict__ Wa, const float* __restrict__ ba,
    const float* __restrict__ Wb, const float* __restrict__ bb_,
    const float* __restrict__ Wc, const float* __restrict__ bc,
    const float* __restrict__ resid, float* __restrict__ outF)
{
    __shared__ __half sA[128*72];
    __shared__ __half sB[64*72];
    const float* X = OUTPROJ ? (const float*)g_x : Xin;   // device-side symbol!
    const int m0 = blockIdx.x * 128, j0 = blockIdx.y * 64;
    const int pz = blockIdx.z;
    const float* W    = (pz == 0) ? Wa : (pz == 1) ? Wb : Wc;
    const float* bias = (pz == 0) ? ba : (pz == 1) ? bb_ : bc;
    __half* outH      = (pz == 0) ? g_q : (pz == 1) ? g_k : g_v;
    const float osc   = (!OUTPROJ && pz == 0) ? SCALE : 1.0f;

    const int tid = threadIdx.x, lane = tid & 31, wid = tid >> 5;
    const int wm = wid >> 1, wn = wid & 1;

    float acc[2][4][4];
#pragma unroll
    for (int m = 0; m < 2; m++)
#pragma unroll
        for (int nt = 0; nt < 4; nt++)
#pragma unroll
            for (int i = 0; i < 4; i++) acc[m][nt][i] = 0.f;

    for (int k0 = 0; k0 < NC; k0 += 64){
        __syncthreads();
#pragma unroll
        for (int i = 0; i < 8; i++){
            int e = tid + i*256, r = e >> 4, c4 = e & 15;
            float4 v = *(const float4*)&X[(size_t)(m0 + r)*NC + k0 + c4*4];
            *(__half2*)&sA[r*72 + c4*4]     = __floats2half2_rn(v.x, v.y);
            *(__half2*)&sA[r*72 + c4*4 + 2] = __floats2half2_rn(v.z, v.w);
        }
#pragma unroll
        for (int i = 0; i < 4; i++){
            int e = tid + i*256, r = e >> 4, c4 = e & 15;
            float4 v = *(const float4*)&W[(size_t)(j0 + r)*NC + k0 + c4*4];
            *(__half2*)&sB[r*72 + c4*4]     = __floats2half2_rn(v.x, v.y);
            *(__half2*)&sB[r*72 + c4*4 + 2] = __floats2half2_rn(v.z, v.w);
        }
        __syncthreads();
#pragma unroll
        for (int kk = 0; kk < 4; kk++){
            int dc = kk*16 + 2*(lane & 3);
            unsigned a[2][4], bb[4][2];
#pragma unroll
            for (int m = 0; m < 2; m++){
                int r = wm*32 + m*16 + (lane >> 2);
                a[m][0] = *(const unsigned*)&sA[r*72 + dc];
                a[m][1] = *(const unsigned*)&sA[(r + 8)*72 + dc];
                a[m][2] = *(const unsigned*)&sA[r*72 + dc + 8];
                a[m][3] = *(const unsigned*)&sA[(r + 8)*72 + dc + 8];
            }
#pragma unroll
            for (int nt = 0; nt < 4; nt++){
                int rj = wn*32 + nt*8 + (lane >> 2);
                bb[nt][0] = *(const unsigned*)&sB[rj*72 + dc];
                bb[nt][1] = *(const unsigned*)&sB[rj*72 + dc + 8];
            }
#pragma unroll
            for (int m = 0; m < 2; m++)
#pragma unroll
                for (int nt = 0; nt < 4; nt++)
                    mma16816(acc[m][nt], a[m], bb[nt][0], bb[nt][1]);
        }
    }

#pragma unroll
    for (int m = 0; m < 2; m++)
#pragma unroll
        for (int nt = 0; nt < 4; nt++){
            int row = m0 + wm*32 + m*16 + (lane >> 2);
            int col = j0 + wn*32 + nt*8 + 2*(lane & 3);
            float b0f = bias[col], b1f = bias[col + 1];
#pragma unroll
            for (int rg = 0; rg < 2; rg++){
                int rr = row + rg*8;
                if (OUTPROJ){
                    float2 o;
                    o.x = acc[m][nt][rg*2 + 0] + b0f + resid[(size_t)rr*NC + col];
                    o.y = acc[m][nt][rg*2 + 1] + b1f + resid[(size_t)rr*NC + col + 1];
                    *(float2*)&outF[(size_t)rr*NC + col] = o;
                } else {
                    int bb2 = rr >> 11, n = rr & (NT-1);
                    int hh = col >> 5, dd = col & 31;
                    size_t addr = ((size_t)(bb2*NH + hh)*NT + n)*DH + dd;
                    *(__half2*)&outH[addr] =
                        __floats2half2_rn((acc[m][nt][rg*2 + 0] + b0f)*osc,
                                          (acc[m][nt][rg*2 + 1] + b1f)*osc);
                }
            }
        }
}

// ------------- fused attention (TQ=32, 512 threads, double-buffered) -------------
#define TQ 32
#define CHUNK 512
#define NCH (NT/CHUNK)                       // 4
#define NWARP 16
#define SS_STRIDE 2056
#define SK_STRIDE 40
#define KVBUF (CHUNK*SK_STRIDE)              // halves per buffer
#define OFF_S   0
#define SZ_S    (TQ*SS_STRIDE*2)             // 131584
#define OFF_KV  (SZ_S)
#define SZ_KV   (2*KVBUF*2)                  // 81920
#define OFF_Q   (OFF_KV + SZ_KV)             // 213504
#define SZ_Q    (TQ*SK_STRIDE*2)             // 2560
#define OFF_SUM (OFF_Q + SZ_Q)               // 216064
#define SMEM_ATTN (OFF_SUM + NWARP*TQ*4)     // 218112 -> 1 CTA/SM

__global__ __launch_bounds__(512, 1) void attn_kernel(float* __restrict__ attn_out)
{
    extern __shared__ char smem[];
    __half* sS   = (__half*)(smem + OFF_S);
    __half* sKV  = (__half*)(smem + OFF_KV);   // [2][KVBUF]
    __half* sQ   = (__half*)(smem + OFF_Q);
    float*  sSum = (float*)(smem + OFF_SUM);

    const int h = blockIdx.x, qt = blockIdx.y, b = blockIdx.z;
    const int bh = b*NH + h;
    const int q0 = qt*TQ;
    const int tid = threadIdx.x, lane = tid & 31, wid = tid >> 5;

    const __half* gQ = g_q + ((size_t)bh*NT + q0)*DH;
    const __half* gK = g_k + (size_t)bh*NT*DH;
    const __half* gV = g_v + (size_t)bh*NT*DH;

    if (tid < 128){
        int r = tid >> 2, seg = tid & 3;
        *(uint4*)&sQ[r*SK_STRIDE + seg*8] = *(const uint4*)&gQ[r*DH + seg*8];
    }

    const int ld_r = tid >> 2, ld_seg = tid & 3;   // 512 rows x 4 segs / 512 thr = 4 CPA16

    // ---- Phase 1: E = exp(Q K^T), double-buffered K ----
    {
        __half* buf = sKV;
#pragma unroll
        for (int i = 0; i < 4; i++){
            int r = ld_r + i*128;
            CPA16(s2u(&buf[r*SK_STRIDE + ld_seg*8]), &gK[(size_t)r*DH + ld_seg*8]);
        }
        CPA_COMMIT();
    }
    unsigned aq[2][2][4];
    float s0 = 0.f, s1 = 0.f, s2 = 0.f, s3 = 0.f;
    for (int ct = 0; ct < NCH; ct++){
        __syncthreads();   // prev compute done -> safe to overwrite idle buffer
        if (ct + 1 < NCH){
            __half* buf = sKV + ((ct + 1) & 1)*KVBUF;
#pragma unroll
            for (int i = 0; i < 4; i++){
                int r = ld_r + i*128;
                CPA16(s2u(&buf[r*SK_STRIDE + ld_seg*8]),
                      &gK[(size_t)((ct + 1)*CHUNK + r)*DH + ld_seg*8]);
            }
            CPA_COMMIT();
            CPA_WAIT1();
        } else {
            CPA_WAIT0();
        }
        __syncthreads();   // chunk ct visible to all
        const __half* kb = sKV + (ct & 1)*KVBUF;
        if (ct == 0){
            uint32_t qa0 = s2u(&sQ[(lane & 15)*SK_STRIDE + 8*(lane >> 4)]);
            ldsm_x4(aq[0][0], qa0);
            ldsm_x4(aq[0][1], qa0 + 32);                       // rows 0-15, k16-31
            uint32_t qa1 = qa0 + 16*SK_STRIDE*2;
            ldsm_x4(aq[1][0], qa1);
            ldsm_x4(aq[1][1], qa1 + 32);                       // rows 16-31
        }
#pragma unroll
        for (int nt = 0; nt < 4; nt++){
            int t0 = wid*32 + nt*8;
            uint32_t ba = s2u(&kb[(t0 + (lane & 7))*SK_STRIDE + 8*((lane >> 3) & 1)]);
            float c0[4] = {0.f,0.f,0.f,0.f}, c1[4] = {0.f,0.f,0.f,0.f};
            unsigned b0, b1;
            ldsm_x2(b0, b1, ba);
            mma16816(c0, aq[0][0], b0, b1);
            mma16816(c1, aq[1][0], b0, b1);
            ldsm_x2(b0, b1, ba + 32);
            mma16816(c0, aq[0][1], b0, b1);
            mma16816(c1, aq[1][1], b0, b1);
            float e00 = fast_ex2(c0[0]*L2E), e01 = fast_ex2(c0[1]*L2E);
            float e02 = fast_ex2(c0[2]*L2E), e03 = fast_ex2(c0[3]*L2E);
            float e10 = fast_ex2(c1[0]*L2E), e11 = fast_ex2(c1[1]*L2E);
            float e12 = fast_ex2(c1[2]*L2E), e13 = fast_ex2(c1[3]*L2E);
            s0 += e00 + e01; s1 += e02 + e03;
            s2 += e10 + e11; s3 += e12 + e13;
            int gc = ct*CHUNK + t0 + 2*(lane & 3);
            int r0 = lane >> 2;
            *(__half2*)&sS[(r0     )*SS_STRIDE + gc] = __floats2half2_rn(e00, e01);
            *(__half2*)&sS[(r0 +  8)*SS_STRIDE + gc] = __floats2half2_rn(e02, e03);
            *(__half2*)&sS[(r0 + 16)*SS_STRIDE + gc] = __floats2half2_rn(e10, e11);
            *(__half2*)&sS[(r0 + 24)*SS_STRIDE + gc] = __floats2half2_rn(e12, e13);
        }
    }
    // reduce row partials across the 4 lanes sharing a row, stage per warp
    s0 += __shfl_xor_sync(0xffffffffu, s0, 1); s0 += __shfl_xor_sync(0xffffffffu, s0, 2);
    s1 += __shfl_xor_sync(0xffffffffu, s1, 1); s1 += __shfl_xor_sync(0xffffffffu, s1, 2);
    s2 += __shfl_xor_sync(0xffffffffu, s2, 1); s2 += __shfl_xor_sync(0xffffffffu, s2, 2);
    s3 += __shfl_xor_sync(0xffffffffu, s3, 1); s3 += __shfl_xor_sync(0xffffffffu, s3, 2);
    if ((lane & 3) == 0){
        int r0 = lane >> 2;
        sSum[wid*TQ + r0]      = s0;
        sSum[wid*TQ + r0 + 8]  = s1;
        sSum[wid*TQ + r0 + 16] = s2;
        sSum[wid*TQ + r0 + 24] = s3;
    }
    __syncthreads();   // sS (all E) + sSum visible

    // prefetch V chunk 0 while phase 2 runs
    {
        __half* buf = sKV;
#pragma unroll
        for (int i = 0; i < 4; i++){
            int r = ld_r + i*128;
            CPA16(s2u(&buf[r*SK_STRIDE + ld_seg*8]), &gV[(size_t)r*DH + ld_seg*8]);
        }
        CPA_COMMIT();
    }

    // ---- Phase 2 (2 rows per warp): icm from g_cmp (warp max-reduce),
    //      inv from staged partials; vectorized normalize ----
#pragma unroll
    for (int rr = 0; rr < 2; rr++){
        int row = wid*2 + rr;
        __half* srow = &sS[row*SS_STRIDE];
        float sum = 0.f;
#pragma unroll
        for (int w = 0; w < NWARP; w++) sum += sSum[w*TQ + row];
        const float inv = 1.0f / sum;
        // inline column-max finalize: max over 32 k-slice partials (exact)
        float cmv = g_cmp[((size_t)b*32 + lane)*NT + q0 + row];
#pragma unroll
        for (int o = 16; o > 0; o >>= 1) cmv = fmaxf(cmv, __shfl_xor_sync(0xffffffffu, cmv, o));
        const __half2 inv2 = __float2half2_rn(inv / cmv);
        const __half* mrow = g_mh + ((size_t)b*NT + q0 + row)*NT;
        float* orow = attn_out + ((size_t)bh*NT + q0 + row)*NT;
#pragma unroll 4
        for (int j = lane; j < NT/8; j += 32){
            uint4 u = *(uint4*)&srow[j*8];
            uint4 mu = *(const uint4*)&mrow[j*8];
            __half2 e0 = *(__half2*)&u.x, e1 = *(__half2*)&u.y;
            __half2 e2 = *(__half2*)&u.z, e3 = *(__half2*)&u.w;
            float2 f0 = __half22float2(e0), f1 = __half22float2(e1);
            float2 f2 = __half22float2(e2), f3 = __half22float2(e3);
            float4 v0, v1;
            v0.x = f0.x*inv; v0.y = f0.y*inv; v0.z = f1.x*inv; v0.w = f1.y*inv;
            v1.x = f2.x*inv; v1.y = f2.y*inv; v1.z = f3.x*inv; v1.w = f3.y*inv;
            *(float4*)&orow[j*8]     = v0;
            *(float4*)&orow[j*8 + 4] = v1;
            __half2 p0 = __hmul2(__hmul2(e0, *(__half2*)&mu.x), inv2);
            __half2 p1 = __hmul2(__hmul2(e1, *(__half2*)&mu.y), inv2);
            __half2 p2 = __hmul2(__hmul2(e2, *(__half2*)&mu.z), inv2);
            __half2 p3 = __hmul2(__hmul2(e3, *(__half2*)&mu.w), inv2);
            uint4 w;
            w.x = *reinterpret_cast<unsigned*>(&p0);
            w.y = *reinterpret_cast<unsigned*>(&p1);
            w.z = *reinterpret_cast<unsigned*>(&p2);
            w.w = *reinterpret_cast<unsigned*>(&p3);
            *(uint4*)&srow[j*8] = w;
        }
    }

    // ---- Phase 3: pure MMA — A = masked probs (sS), B = V (double-buffered) ----
    float acc[2][4][4];
#pragma unroll
    for (int rt = 0; rt < 2; rt++)
#pragma unroll
        for (int nt = 0; nt < 4; nt++)
#pragma unroll
            for (int i = 0; i < 4; i++) acc[rt][nt][i] = 0.f;

    for (int ct = 0; ct < NCH; ct++){
        __syncthreads();
        if (ct + 1 < NCH){
            __half* buf = sKV + ((ct + 1) & 1)*KVBUF;
#pragma unroll
            for (int i = 0; i < 4; i++){
                int r = ld_r + i*128;
                CPA16(s2u(&buf[r*SK_STRIDE + ld_seg*8]),
                      &gV[(size_t)((ct + 1)*CHUNK + r)*DH + ld_seg*8]);
            }
            CPA_COMMIT();
            CPA_WAIT1();
        } else {
            CPA_WAIT0();
        }
        __syncthreads();
        const __half* vb = sKV + (ct & 1)*KVBUF;
#pragma unroll
        for (int kb = 0; kb < 2; kb++){
            int tc = wid*32 + kb*16;
            int gcol = ct*CHUNK + tc;
            unsigned a0[4], a1[4];
            ldsm_x4(a0, s2u(&sS[(lane & 15)*SS_STRIDE + gcol + 8*(lane >> 4)]));
            ldsm_x4(a1, s2u(&sS[((lane & 15) + 16)*SS_STRIDE + gcol + 8*(lane >> 4)]));
#pragma unroll
            for (int nt = 0; nt < 4; nt++){
                unsigned b0, b1;
                ldsm_x2t(b0, b1, s2u(&vb[(tc + (lane & 15))*SK_STRIDE + nt*8]));
                mma16816(acc[0][nt], a0, b0, b1);
                mma16816(acc[1][nt], a1, b0, b1);
            }
        }
    }

    // ---- cross-warp AV reduction (reuse sS region: 16 x 1024 floats = 64KB) ----
    __syncthreads();
    const int r_lo = lane >> 2, r_hi = r_lo + 8;
    float* sRed = (float*)(smem + OFF_S);
#pragma unroll
    for (int rt = 0; rt < 2; rt++)
#pragma unroll
        for (int nt = 0; nt < 4; nt++){
            int dd = nt*8 + 2*(lane & 3);
            float2 v0; v0.x = acc[rt][nt][0]; v0.y = acc[rt][nt][1];
            float2 v1; v1.x = acc[rt][nt][2]; v1.y = acc[rt][nt][3];
            *(float2*)&sRed[wid*1024 + (r_lo + rt*16)*32 + dd] = v0;
            *(float2*)&sRed[wid*1024 + (r_hi + rt*16)*32 + dd] = v1;
        }
    __syncthreads();
#pragma unroll
    for (int ii = 0; ii < 2; ii++){
        int i = tid + ii*512;
        float s = 0.f;
#pragma unroll
        for (int w = 0; w < NWARP; w++) s += sRed[w*1024 + i];
        int qq = i >> 5, dd = i & 31;
        g_x[((size_t)b*NT + q0 + qq)*NC + h*DH + dd] = s;
    }
}

// ---------------- launch ----------------
extern "C" void kernel_launch(void* const* d_in, const int* in_sizes, int n_in,
                              void* d_out, int out_size)
{
    const float* query = (const float*)d_in[0];
    const float* mask  = (const float*)d_in[1];
    const float* Wq = (const float*)d_in[2]; const float* bq = (const float*)d_in[3];
    const float* Wk = (const float*)d_in[4]; const float* bk = (const float*)d_in[5];
    const float* Wv = (const float*)d_in[6]; const float* bv = (const float*)d_in[7];
    const float* Wo = (const float*)d_in[8]; const float* bo = (const float*)d_in[9];

    float* out_query = (float*)d_out;
    float* attn_vis  = out_query + (size_t)NB*NT*NC;

    cudaFuncSetAttribute(attn_kernel, cudaFuncAttributeMaxDynamicSharedMemorySize, SMEM_ATTN);

    mask_prep_kernel<<<dim3(NT/64, NT/64, NB), 256>>>(mask);
    gemm_kernel<false><<<dim3(NB*NT/128, NC/64, 3), 256>>>(
        query, Wq, bq, Wk, bk, Wv, bv, nullptr, nullptr);
    attn_kernel<<<dim3(NH, NT/TQ, NB), 512, SMEM_ATTN>>>(attn_vis);
    gemm_kernel<true><<<dim3(NB*NT/128, NC/64, 1), 256>>>(
        nullptr, Wo, bo, nullptr, nullptr, nullptr, nullptr, query, out_query);
}

// round 13
// speedup vs baseline: 1.1318x; 1.0465x over previous
#include <cuda_runtime.h>
#include <cuda_fp16.h>
#include <cstdint>

#define NB 4
#define NH 8
#define NT 2048
#define DH 32
#define NC 256
#define SCALE 0.17677669529663687f
#define L2E   1.4426950408889634f

static __device__ __half g_q[(size_t)NB*NH*NT*DH];
static __device__ __half g_k[(size_t)NB*NH*NT*DH];
static __device__ __half g_v[(size_t)NB*NH*NT*DH];
static __device__ float  g_x[(size_t)NB*NT*NC];
static __device__ float  g_icm[NB*NT];
static __device__ float  g_cmp[(size_t)NB*32*NT];
static __device__ __half g_mh[(size_t)NB*NT*NT];   // transposed, UNnormalized

__device__ __forceinline__ float fast_ex2(float x){
    float y; asm("ex2.approx.ftz.f32 %0, %1;" : "=f"(y) : "f"(x)); return y;
}
__device__ __forceinline__ void mma16816(float* c, const unsigned* a, unsigned b0, unsigned b1){
    asm volatile("mma.sync.aligned.m16n8k16.row.col.f32.f16.f16.f32 "
        "{%0,%1,%2,%3},{%4,%5,%6,%7},{%8,%9},{%0,%1,%2,%3};"
        : "+f"(c[0]), "+f"(c[1]), "+f"(c[2]), "+f"(c[3])
        : "r"(a[0]), "r"(a[1]), "r"(a[2]), "r"(a[3]), "r"(b0), "r"(b1));
}
__device__ __forceinline__ uint32_t s2u(const void* p){
    return (uint32_t)__cvta_generic_to_shared(p);
}
__device__ __forceinline__ void ldsm_x4(unsigned* a, uint32_t addr){
    asm volatile("ldmatrix.sync.aligned.m8n8.x4.shared.b16 {%0,%1,%2,%3}, [%4];"
        : "=r"(a[0]),"=r"(a[1]),"=r"(a[2]),"=r"(a[3]) : "r"(addr));
}
__device__ __forceinline__ void ldsm_x2(unsigned& b0, unsigned& b1, uint32_t addr){
    asm volatile("ldmatrix.sync.aligned.m8n8.x2.shared.b16 {%0,%1}, [%2];"
        : "=r"(b0),"=r"(b1) : "r"(addr));
}
__device__ __forceinline__ void ldsm_x2t(unsigned& b0, unsigned& b1, uint32_t addr){
    asm volatile("ldmatrix.sync.aligned.m8n8.x2.trans.shared.b16 {%0,%1}, [%2];"
        : "=r"(b0),"=r"(b1) : "r"(addr));
}
#define CPA16(dst, src) asm volatile("cp.async.cg.shared.global [%0], [%1], 16;" :: "r"(dst), "l"(src))
#define CPA_COMMIT() asm volatile("cp.async.commit_group;")
#define CPA_WAIT1()  asm volatile("cp.async.wait_group 1;" ::: "memory")
#define CPA_WAIT0()  asm volatile("cp.async.wait_group 0;" ::: "memory")

// ---------------- fused prep: QKV GEMM blocks + mask transpose blocks ----------------
// blocks [0,768): OUT = X @ W^T + bias (W in {Wq,Wk,Wv}), half [B,H,N,Dh], Q pre-scaled
// blocks [768,4864): 64x64 mask tile transpose -> g_mh + column-max partial -> g_cmp
__global__ __launch_bounds__(256) void prep_kernel(
    const float* __restrict__ mask,
    const float* __restrict__ X,
    const float* __restrict__ Wq, const float* __restrict__ bq,
    const float* __restrict__ Wk, const float* __restrict__ bk,
    const float* __restrict__ Wv, const float* __restrict__ bv)
{
    const int tid = threadIdx.x;
    if (blockIdx.x < 768){
        __shared__ __half sA[128*72];
        __shared__ __half sB[64*72];
        const int bx = blockIdx.x;
        const int m0 = (bx & 63) * 128;
        const int j0 = ((bx >> 6) & 3) * 64;
        const int pz = bx >> 8;
        const float* W    = (pz == 0) ? Wq : (pz == 1) ? Wk : Wv;
        const float* bias = (pz == 0) ? bq : (pz == 1) ? bk : bv;
        __half* outH      = (pz == 0) ? g_q : (pz == 1) ? g_k : g_v;
        const float osc   = (pz == 0) ? SCALE : 1.0f;

        const int lane = tid & 31, wid = tid >> 5;
        const int wm = wid >> 1, wn = wid & 1;

        float acc[2][4][4];
#pragma unroll
        for (int m = 0; m < 2; m++)
#pragma unroll
            for (int nt = 0; nt < 4; nt++)
#pragma unroll
                for (int i = 0; i < 4; i++) acc[m][nt][i] = 0.f;

        for (int k0 = 0; k0 < NC; k0 += 64){
            __syncthreads();
#pragma unroll
            for (int i = 0; i < 8; i++){
                int e = tid + i*256, r = e >> 4, c4 = e & 15;
                float4 v = *(const float4*)&X[(size_t)(m0 + r)*NC + k0 + c4*4];
                *(__half2*)&sA[r*72 + c4*4]     = __floats2half2_rn(v.x, v.y);
                *(__half2*)&sA[r*72 + c4*4 + 2] = __floats2half2_rn(v.z, v.w);
            }
#pragma unroll
            for (int i = 0; i < 4; i++){
                int e = tid + i*256, r = e >> 4, c4 = e & 15;
                float4 v = *(const float4*)&W[(size_t)(j0 + r)*NC + k0 + c4*4];
                *(__half2*)&sB[r*72 + c4*4]     = __floats2half2_rn(v.x, v.y);
                *(__half2*)&sB[r*72 + c4*4 + 2] = __floats2half2_rn(v.z, v.w);
            }
            __syncthreads();
#pragma unroll
            for (int kk = 0; kk < 4; kk++){
                int dc = kk*16 + 2*(lane & 3);
                unsigned a[2][4], bb[4][2];
#pragma unroll
                for (int m = 0; m < 2; m++){
                    int r = wm*32 + m*16 + (lane >> 2);
                    a[m][0] = *(const unsigned*)&sA[r*72 + dc];
                    a[m][1] = *(const unsigned*)&sA[(r + 8)*72 + dc];
                    a[m][2] = *(const unsigned*)&sA[r*72 + dc + 8];
                    a[m][3] = *(const unsigned*)&sA[(r + 8)*72 + dc + 8];
                }
#pragma unroll
                for (int nt = 0; nt < 4; nt++){
                    int rj = wn*32 + nt*8 + (lane >> 2);
                    bb[nt][0] = *(const unsigned*)&sB[rj*72 + dc];
                    bb[nt][1] = *(const unsigned*)&sB[rj*72 + dc + 8];
                }
#pragma unroll
                for (int m = 0; m < 2; m++)
#pragma unroll
                    for (int nt = 0; nt < 4; nt++)
                        mma16816(acc[m][nt], a[m], bb[nt][0], bb[nt][1]);
            }
        }

#pragma unroll
        for (int m = 0; m < 2; m++)
#pragma unroll
            for (int nt = 0; nt < 4; nt++){
                int row = m0 + wm*32 + m*16 + (lane >> 2);
                int col = j0 + wn*32 + nt*8 + 2*(lane & 3);
                float b0f = bias[col], b1f = bias[col + 1];
#pragma unroll
                for (int rg = 0; rg < 2; rg++){
                    int rr = row + rg*8;
                    int bb2 = rr >> 11, n = rr & (NT-1);
                    int hh = col >> 5, dd = col & 31;
                    size_t addr = ((size_t)(bb2*NH + hh)*NT + n)*DH + dd;
                    *(__half2*)&outH[addr] =
                        __floats2half2_rn((acc[m][nt][rg*2 + 0] + b0f)*osc,
                                          (acc[m][nt][rg*2 + 1] + b1f)*osc);
                }
            }
    } else {
        __shared__ float t[64][65];
        __shared__ float pm[8][64];
        const int idx = blockIdx.x - 768;
        const int k0 = (idx & 31) * 64;
        const int q0 = ((idx >> 5) & 31) * 64;
        const int b  = idx >> 10;
#pragma unroll
        for (int i = 0; i < 4; i++){
            int e = tid + i*256, r = e >> 4, c4 = e & 15;
            float4 v = *(const float4*)&mask[(size_t)b*NT*NT + (size_t)(k0 + r)*NT + q0 + c4*4];
            t[r][c4*4    ] = v.x; t[r][c4*4 + 1] = v.y;
            t[r][c4*4 + 2] = v.z; t[r][c4*4 + 3] = v.w;
        }
        __syncthreads();
#pragma unroll
        for (int i = 0; i < 2; i++){
            int idx2 = tid + i*256;
            int q = idx2 >> 3, seg = idx2 & 7;
            float f0 = t[seg*8    ][q], f1 = t[seg*8 + 1][q];
            float f2 = t[seg*8 + 2][q], f3 = t[seg*8 + 3][q];
            float f4 = t[seg*8 + 4][q], f5 = t[seg*8 + 5][q];
            float f6 = t[seg*8 + 6][q], f7 = t[seg*8 + 7][q];
            __half2 h0 = __floats2half2_rn(f0, f1), h1 = __floats2half2_rn(f2, f3);
            __half2 h2 = __floats2half2_rn(f4, f5), h3 = __floats2half2_rn(f6, f7);
            uint4 w;
            w.x = *reinterpret_cast<unsigned*>(&h0);
            w.y = *reinterpret_cast<unsigned*>(&h1);
            w.z = *reinterpret_cast<unsigned*>(&h2);
            w.w = *reinterpret_cast<unsigned*>(&h3);
            *(uint4*)&g_mh[((size_t)b*NT + q0 + q)*NT + k0 + seg*8] = w;
            float m = fmaxf(fmaxf(fmaxf(f0, f1), fmaxf(f2, f3)),
                            fmaxf(fmaxf(f4, f5), fmaxf(f6, f7)));
            pm[seg][q] = m;
        }
        __syncthreads();
        if (tid < 64){
            float m3 = pm[0][tid];
#pragma unroll
            for (int w2 = 1; w2 < 8; w2++) m3 = fmaxf(m3, pm[w2][tid]);
            g_cmp[((size_t)b*32 + (k0 >> 6))*NT + q0 + tid] = m3;
        }
    }
}

__global__ void colmax_fin(){
    int i = blockIdx.x*256 + threadIdx.x;
    int b = i >> 11, q = i & (NT-1);
    float mx = 0.f;
#pragma unroll
    for (int s = 0; s < 32; s++) mx = fmaxf(mx, g_cmp[((size_t)b*32 + s)*NT + q]);
    g_icm[i] = 1.0f / mx;
}

// ---------------- out-proj GEMM: out = g_x @ Wo^T + bo + query ----------------
__global__ __launch_bounds__(256) void outproj_kernel(
    const float* __restrict__ Wo, const float* __restrict__ bo,
    const float* __restrict__ resid, float* __restrict__ outF)
{
    __shared__ __half sA[128*72];
    __shared__ __half sB[64*72];
    const float* X = (const float*)g_x;   // device-side symbol!
    const int m0 = blockIdx.x * 128, j0 = blockIdx.y * 64;

    const int tid = threadIdx.x, lane = tid & 31, wid = tid >> 5;
    const int wm = wid >> 1, wn = wid & 1;

    float acc[2][4][4];
#pragma unroll
    for (int m = 0; m < 2; m++)
#pragma unroll
        for (int nt = 0; nt < 4; nt++)
#pragma unroll
            for (int i = 0; i < 4; i++) acc[m][nt][i] = 0.f;

    for (int k0 = 0; k0 < NC; k0 += 64){
        __syncthreads();
#pragma unroll
        for (int i = 0; i < 8; i++){
            int e = tid + i*256, r = e >> 4, c4 = e & 15;
            float4 v = *(const float4*)&X[(size_t)(m0 + r)*NC + k0 + c4*4];
            *(__half2*)&sA[r*72 + c4*4]     = __floats2half2_rn(v.x, v.y);
            *(__half2*)&sA[r*72 + c4*4 + 2] = __floats2half2_rn(v.z, v.w);
        }
#pragma unroll
        for (int i = 0; i < 4; i++){
            int e = tid + i*256, r = e >> 4, c4 = e & 15;
            float4 v = *(const float4*)&Wo[(size_t)(j0 + r)*NC + k0 + c4*4];
            *(__half2*)&sB[r*72 + c4*4]     = __floats2half2_rn(v.x, v.y);
            *(__half2*)&sB[r*72 + c4*4 + 2] = __floats2half2_rn(v.z, v.w);
        }
        __syncthreads();
#pragma unroll
        for (int kk = 0; kk < 4; kk++){
            int dc = kk*16 + 2*(lane & 3);
            unsigned a[2][4], bb[4][2];
#pragma unroll
            for (int m = 0; m < 2; m++){
                int r = wm*32 + m*16 + (lane >> 2);
                a[m][0] = *(const unsigned*)&sA[r*72 + dc];
                a[m][1] = *(const unsigned*)&sA[(r + 8)*72 + dc];
                a[m][2] = *(const unsigned*)&sA[r*72 + dc + 8];
                a[m][3] = *(const unsigned*)&sA[(r + 8)*72 + dc + 8];
            }
#pragma unroll
            for (int nt = 0; nt < 4; nt++){
                int rj = wn*32 + nt*8 + (lane >> 2);
                bb[nt][0] = *(const unsigned*)&sB[rj*72 + dc];
                bb[nt][1] = *(const unsigned*)&sB[rj*72 + dc + 8];
            }
#pragma unroll
            for (int m = 0; m < 2; m++)
#pragma unroll
                for (int nt = 0; nt < 4; nt++)
                    mma16816(acc[m][nt], a[m], bb[nt][0], bb[nt][1]);
        }
    }

#pragma unroll
    for (int m = 0; m < 2; m++)
#pragma unroll
        for (int nt = 0; nt < 4; nt++){
            int row = m0 + wm*32 + m*16 + (lane >> 2);
            int col = j0 + wn*32 + nt*8 + 2*(lane & 3);
            float b0f = bo[col], b1f = bo[col + 1];
#pragma unroll
            for (int rg = 0; rg < 2; rg++){
                int rr = row + rg*8;
                float2 o;
                o.x = acc[m][nt][rg*2 + 0] + b0f + resid[(size_t)rr*NC + col];
                o.y = acc[m][nt][rg*2 + 1] + b1f + resid[(size_t)rr*NC + col + 1];
                *(float2*)&outF[(size_t)rr*NC + col] = o;
            }
        }
}

// ------------- fused attention (TQ=32, 512 threads, double-buffered) -------------
#define TQ 32
#define CHUNK 512
#define NCH (NT/CHUNK)                       // 4
#define NWARP 16
#define SS_STRIDE 2056
#define SK_STRIDE 40
#define KVBUF (CHUNK*SK_STRIDE)              // halves per buffer
#define OFF_S   0
#define SZ_S    (TQ*SS_STRIDE*2)             // 131584
#define OFF_KV  (SZ_S)
#define SZ_KV   (2*KVBUF*2)                  // 81920
#define OFF_Q   (OFF_KV + SZ_KV)             // 213504
#define SZ_Q    (TQ*SK_STRIDE*2)             // 2560
#define OFF_SUM (OFF_Q + SZ_Q)               // 216064
#define SMEM_ATTN (OFF_SUM + NWARP*TQ*4)     // 218112 -> 1 CTA/SM

__global__ __launch_bounds__(512, 1) void attn_kernel(float* __restrict__ attn_out)
{
    extern __shared__ char smem[];
    __half* sS   = (__half*)(smem + OFF_S);
    __half* sKV  = (__half*)(smem + OFF_KV);   // [2][KVBUF]
    __half* sQ   = (__half*)(smem + OFF_Q);
    float*  sSum = (float*)(smem + OFF_SUM);

    const int h = blockIdx.x, qt = blockIdx.y, b = blockIdx.z;
    const int bh = b*NH + h;
    const int q0 = qt*TQ;
    const int tid = threadIdx.x, lane = tid & 31, wid = tid >> 5;

    const __half* gQ = g_q + ((size_t)bh*NT + q0)*DH;
    const __half* gK = g_k + (size_t)bh*NT*DH;
    const __half* gV = g_v + (size_t)bh*NT*DH;

    if (tid < 128){
        int r = tid >> 2, seg = tid & 3;
        *(uint4*)&sQ[r*SK_STRIDE + seg*8] = *(const uint4*)&gQ[r*DH + seg*8];
    }

    const int ld_r = tid >> 2, ld_seg = tid & 3;   // 512 rows x 4 segs / 512 thr = 4 CPA16

    // ---- Phase 1: E = exp(Q K^T), double-buffered K ----
    {
        __half* buf = sKV;
#pragma unroll
        for (int i = 0; i < 4; i++){
            int r = ld_r + i*128;
            CPA16(s2u(&buf[r*SK_STRIDE + ld_seg*8]), &gK[(size_t)r*DH + ld_seg*8]);
        }
        CPA_COMMIT();
    }
    unsigned aq[2][2][4];
    float s0 = 0.f, s1 = 0.f, s2 = 0.f, s3 = 0.f;
    for (int ct = 0; ct < NCH; ct++){
        __syncthreads();   // prev compute done -> safe to overwrite idle buffer
        if (ct + 1 < NCH){
            __half* buf = sKV + ((ct + 1) & 1)*KVBUF;
#pragma unroll
            for (int i = 0; i < 4; i++){
                int r = ld_r + i*128;
                CPA16(s2u(&buf[r*SK_STRIDE + ld_seg*8]),
                      &gK[(size_t)((ct + 1)*CHUNK + r)*DH + ld_seg*8]);
            }
            CPA_COMMIT();
            CPA_WAIT1();
        } else {
            CPA_WAIT0();
        }
        __syncthreads();   // chunk ct visible to all
        const __half* kb = sKV + (ct & 1)*KVBUF;
        if (ct == 0){
            uint32_t qa0 = s2u(&sQ[(lane & 15)*SK_STRIDE + 8*(lane >> 4)]);
            ldsm_x4(aq[0][0], qa0);
            ldsm_x4(aq[0][1], qa0 + 32);                       // rows 0-15, k16-31
            uint32_t qa1 = qa0 + 16*SK_STRIDE*2;
            ldsm_x4(aq[1][0], qa1);
            ldsm_x4(aq[1][1], qa1 + 32);                       // rows 16-31
        }
#pragma unroll
        for (int nt = 0; nt < 4; nt++){
            int t0 = wid*32 + nt*8;
            uint32_t ba = s2u(&kb[(t0 + (lane & 7))*SK_STRIDE + 8*((lane >> 3) & 1)]);
            float c0[4] = {0.f,0.f,0.f,0.f}, c1[4] = {0.f,0.f,0.f,0.f};
            unsigned b0, b1;
            ldsm_x2(b0, b1, ba);
            mma16816(c0, aq[0][0], b0, b1);
            mma16816(c1, aq[1][0], b0, b1);
            ldsm_x2(b0, b1, ba + 32);
            mma16816(c0, aq[0][1], b0, b1);
            mma16816(c1, aq[1][1], b0, b1);
            float e00 = fast_ex2(c0[0]*L2E), e01 = fast_ex2(c0[1]*L2E);
            float e02 = fast_ex2(c0[2]*L2E), e03 = fast_ex2(c0[3]*L2E);
            float e10 = fast_ex2(c1[0]*L2E), e11 = fast_ex2(c1[1]*L2E);
            float e12 = fast_ex2(c1[2]*L2E), e13 = fast_ex2(c1[3]*L2E);
            s0 += e00 + e01; s1 += e02 + e03;
            s2 += e10 + e11; s3 += e12 + e13;
            int gc = ct*CHUNK + t0 + 2*(lane & 3);
            int r0 = lane >> 2;
            *(__half2*)&sS[(r0     )*SS_STRIDE + gc] = __floats2half2_rn(e00, e01);
            *(__half2*)&sS[(r0 +  8)*SS_STRIDE + gc] = __floats2half2_rn(e02, e03);
            *(__half2*)&sS[(r0 + 16)*SS_STRIDE + gc] = __floats2half2_rn(e10, e11);
            *(__half2*)&sS[(r0 + 24)*SS_STRIDE + gc] = __floats2half2_rn(e12, e13);
        }
    }
    // reduce row partials across the 4 lanes sharing a row, stage per warp
    s0 += __shfl_xor_sync(0xffffffffu, s0, 1); s0 += __shfl_xor_sync(0xffffffffu, s0, 2);
    s1 += __shfl_xor_sync(0xffffffffu, s1, 1); s1 += __shfl_xor_sync(0xffffffffu, s1, 2);
    s2 += __shfl_xor_sync(0xffffffffu, s2, 1); s2 += __shfl_xor_sync(0xffffffffu, s2, 2);
    s3 += __shfl_xor_sync(0xffffffffu, s3, 1); s3 += __shfl_xor_sync(0xffffffffu, s3, 2);
    if ((lane & 3) == 0){
        int r0 = lane >> 2;
        sSum[wid*TQ + r0]      = s0;
        sSum[wid*TQ + r0 + 8]  = s1;
        sSum[wid*TQ + r0 + 16] = s2;
        sSum[wid*TQ + r0 + 24] = s3;
    }
    __syncthreads();   // sS (all E) + sSum visible

    // prefetch V chunk 0 while phase 2 runs
    {
        __half* buf = sKV;
#pragma unroll
        for (int i = 0; i < 4; i++){
            int r = ld_r + i*128;
            CPA16(s2u(&buf[r*SK_STRIDE + ld_seg*8]), &gV[(size_t)r*DH + ld_seg*8]);
        }
        CPA_COMMIT();
    }

    // ---- Phase 2 (2 rows per warp): inv; vectorized normalize ----
#pragma unroll
    for (int rr = 0; rr < 2; rr++){
        int row = wid*2 + rr;
        __half* srow = &sS[row*SS_STRIDE];
        float sum = 0.f;
#pragma unroll
        for (int w = 0; w < NWARP; w++) sum += sSum[w*TQ + row];
        const float inv = 1.0f / sum;
        const __half2 inv2 = __float2half2_rn(inv * g_icm[b*NT + q0 + row]);
        const __half* mrow = g_mh + ((size_t)b*NT + q0 + row)*NT;
        float* orow = attn_out + ((size_t)bh*NT + q0 + row)*NT;
#pragma unroll 2
        for (int j = lane; j < NT/8; j += 32){
            uint4 u = *(uint4*)&srow[j*8];
            uint4 mu = *(const uint4*)&mrow[j*8];
            __half2 e0 = *(__half2*)&u.x, e1 = *(__half2*)&u.y;
            __half2 e2 = *(__half2*)&u.z, e3 = *(__half2*)&u.w;
            float2 f0 = __half22float2(e0), f1 = __half22float2(e1);
            float2 f2 = __half22float2(e2), f3 = __half22float2(e3);
            float4 v0, v1;
            v0.x = f0.x*inv; v0.y = f0.y*inv; v0.z = f1.x*inv; v0.w = f1.y*inv;
            v1.x = f2.x*inv; v1.y = f2.y*inv; v1.z = f3.x*inv; v1.w = f3.y*inv;
            *(float4*)&orow[j*8]     = v0;
            *(float4*)&orow[j*8 + 4] = v1;
            __half2 p0 = __hmul2(__hmul2(e0, *(__half2*)&mu.x), inv2);
            __half2 p1 = __hmul2(__hmul2(e1, *(__half2*)&mu.y), inv2);
            __half2 p2 = __hmul2(__hmul2(e2, *(__half2*)&mu.z), inv2);
            __half2 p3 = __hmul2(__hmul2(e3, *(__half2*)&mu.w), inv2);
            uint4 w;
            w.x = *reinterpret_cast<unsigned*>(&p0);
            w.y = *reinterpret_cast<unsigned*>(&p1);
            w.z = *reinterpret_cast<unsigned*>(&p2);
            w.w = *reinterpret_cast<unsigned*>(&p3);
            *(uint4*)&srow[j*8] = w;
        }
    }

    // ---- Phase 3: pure MMA — A = masked probs (sS), B = V (double-buffered) ----
    float acc[2][4][4];
#pragma unroll
    for (int rt = 0; rt < 2; rt++)
#pragma unroll
        for (int nt = 0; nt < 4; nt++)
#pragma unroll
            for (int i = 0; i < 4; i++) acc[rt][nt][i] = 0.f;

    for (int ct = 0; ct < NCH; ct++){
        __syncthreads();
        if (ct + 1 < NCH){
            __half* buf = sKV + ((ct + 1) & 1)*KVBUF;
#pragma unroll
            for (int i = 0; i < 4; i++){
                int r = ld_r + i*128;
                CPA16(s2u(&buf[r*SK_STRIDE + ld_seg*8]),
                      &gV[(size_t)((ct + 1)*CHUNK + r)*DH + ld_seg*8]);
            }
            CPA_COMMIT();
            CPA_WAIT1();
        } else {
            CPA_WAIT0();
        }
        __syncthreads();
        const __half* vb = sKV + (ct & 1)*KVBUF;
#pragma unroll
        for (int kb = 0; kb < 2; kb++){
            int tc = wid*32 + kb*16;
            int gcol = ct*CHUNK + tc;
            unsigned a0[4], a1[4];
            ldsm_x4(a0, s2u(&sS[(lane & 15)*SS_STRIDE + gcol + 8*(lane >> 4)]));
            ldsm_x4(a1, s2u(&sS[((lane & 15) + 16)*SS_STRIDE + gcol + 8*(lane >> 4)]));
#pragma unroll
            for (int nt = 0; nt < 4; nt++){
                unsigned b0, b1;
                ldsm_x2t(b0, b1, s2u(&vb[(tc + (lane & 15))*SK_STRIDE + nt*8]));
                mma16816(acc[0][nt], a0, b0, b1);
                mma16816(acc[1][nt], a1, b0, b1);
            }
        }
    }

    // ---- cross-warp AV reduction (reuse sS region: 16 x 1024 floats = 64KB) ----
    __syncthreads();
    const int r_lo = lane >> 2, r_hi = r_lo + 8;
    float* sRed = (float*)(smem + OFF_S);
#pragma unroll
    for (int rt = 0; rt < 2; rt++)
#pragma unroll
        for (int nt = 0; nt < 4; nt++){
            int dd = nt*8 + 2*(lane & 3);
            float2 v0; v0.x = acc[rt][nt][0]; v0.y = acc[rt][nt][1];
            float2 v1; v1.x = acc[rt][nt][2]; v1.y = acc[rt][nt][3];
            *(float2*)&sRed[wid*1024 + (r_lo + rt*16)*32 + dd] = v0;
            *(float2*)&sRed[wid*1024 + (r_hi + rt*16)*32 + dd] = v1;
        }
    __syncthreads();
#pragma unroll
    for (int ii = 0; ii < 2; ii++){
        int i = tid + ii*512;
        float s = 0.f;
#pragma unroll
        for (int w = 0; w < NWARP; w++) s += sRed[w*1024 + i];
        int qq = i >> 5, dd = i & 31;
        g_x[((size_t)b*NT + q0 + qq)*NC + h*DH + dd] = s;
    }
}

// ---------------- launch ----------------
extern "C" void kernel_launch(void* const* d_in, const int* in_sizes, int n_in,
                              void* d_out, int out_size)
{
    const float* query = (const float*)d_in[0];
    const float* mask  = (const float*)d_in[1];
    const float* Wq = (const float*)d_in[2]; const float* bq = (const float*)d_in[3];
    const float* Wk = (const float*)d_in[4]; const float* bk = (const float*)d_in[5];
    const float* Wv = (const float*)d_in[6]; const float* bv = (const float*)d_in[7];
    const float* Wo = (const float*)d_in[8]; const float* bo = (const float*)d_in[9];

    float* out_query = (float*)d_out;
    float* attn_vis  = out_query + (size_t)NB*NT*NC;

    cudaFuncSetAttribute(attn_kernel, cudaFuncAttributeMaxDynamicSharedMemorySize, SMEM_ATTN);

    prep_kernel<<<768 + 4096, 256>>>(mask, query, Wq, bq, Wk, bk, Wv, bv);
    colmax_fin<<<NB*NT/256, 256>>>();
    attn_kernel<<<dim3(NH, NT/TQ, NB), 512, SMEM_ATTN>>>(attn_vis);
    outproj_kernel<<<dim3(NB*NT/128, NC/64), 256>>>(Wo, bo, query, out_query);
}